// round 9
// baseline (speedup 1.0000x reference)
#include <cuda_runtime.h>
#include <cstdint>

// Problem shape (fixed)
#define BB 2
#define SS 2048
#define EE 1024
#define HH 16
#define DD 64
#define MTOT (BB*SS)   // 4096

// Scratch (device globals)
__device__ float g_xr[MTOT*EE];        // x rounded to tf32 grid
__device__ float g_wt[3*EE*EE];        // W{q,k,v}^T: [which][n=h*64+d][e], rna-rounded
__device__ float g_wpt[EE*EE];         // Wp^T: [n][k], rna-rounded
__device__ float g_q[BB*HH*SS*DD];     // [B,H,S,D], rna-rounded
__device__ float g_k[BB*HH*SS*DD];
__device__ float g_v[BB*HH*SS*DD];
__device__ float g_attn[BB*SS*HH*DD];  // [B,S,H*D], rna-rounded

// ============================ helpers ============================
__device__ __forceinline__ uint32_t smem_to_u32(const void* p) {
    uint32_t a;
    asm("{ .reg .u64 t; cvta.to.shared.u64 t, %1; cvt.u32.u64 %0, t; }" : "=r"(a) : "l"(p));
    return a;
}
__device__ __forceinline__ float rna_tf32(float v) {
    float r; asm("cvt.rna.tf32.f32 %0, %1;" : "=f"(r) : "f"(v)); return r;
}
__device__ __forceinline__ void ldgsts16(uint32_t s, const float* g) {
    asm volatile("cp.async.cg.shared.global [%0], [%1], 16;" :: "r"(s), "l"(g) : "memory");
}
#define CP_COMMIT() asm volatile("cp.async.commit_group;" ::: "memory")
#define CP_WAIT2()  asm volatile("cp.async.wait_group 2;" ::: "memory")

// m16n8k8 tf32 mma: D += A*B   (fragment conventions validated in R5/R6)
__device__ __forceinline__ void mma16n8k8(float* d, const uint32_t* a, const uint32_t* b) {
    asm volatile(
        "mma.sync.aligned.m16n8k8.row.col.f32.tf32.tf32.f32 "
        "{%0,%1,%2,%3}, {%4,%5,%6,%7}, {%8,%9}, {%0,%1,%2,%3};\n"
        : "+f"(d[0]), "+f"(d[1]), "+f"(d[2]), "+f"(d[3])
        : "r"(a[0]), "r"(a[1]), "r"(a[2]), "r"(a[3]), "r"(b[0]), "r"(b[1]));
}

// ============================ prep kernels ============================
__global__ __launch_bounds__(256) void round_x_kernel(const float* __restrict__ x)
{
    int i = blockIdx.x * blockDim.x + threadIdx.x;
    const int n4 = MTOT * EE / 4;
    for (; i < n4; i += gridDim.x * blockDim.x) {
        float4 v = ((const float4*)x)[i];
        v.x = rna_tf32(v.x); v.y = rna_tf32(v.y);
        v.z = rna_tf32(v.z); v.w = rna_tf32(v.w);
        ((float4*)g_xr)[i] = v;
    }
}

__global__ __launch_bounds__(256) void transpose_w_kernel(
    const float* __restrict__ Wq, const float* __restrict__ Wk, const float* __restrict__ Wv)
{
    __shared__ float t[32][33];
    const int zc = blockIdx.z;              // 0..47
    const int which = zc >> 4, h = zc & 15;
    const float* W = ((which == 0) ? Wq : (which == 1) ? Wk : Wv) + (size_t)h * EE * DD;
    const int e0 = blockIdx.x * 32, d0 = blockIdx.y * 32;
    const int tx = threadIdx.x & 31, ty8 = threadIdx.x >> 5;
    #pragma unroll
    for (int i = 0; i < 4; i++) {
        int e = ty8 + i * 8;
        t[e][tx] = rna_tf32(W[(size_t)(e0 + e) * DD + d0 + tx]);
    }
    __syncthreads();
    float* dst = g_wt + (size_t)which * EE * EE;
    #pragma unroll
    for (int i = 0; i < 4; i++) {
        int dr = ty8 + i * 8;
        dst[(size_t)(h * DD + d0 + dr) * EE + e0 + tx] = t[tx][dr];
    }
}

__global__ __launch_bounds__(256) void transpose_wp_kernel(const float* __restrict__ Wp)
{
    __shared__ float t[32][33];
    const int k0 = blockIdx.x * 32, n0 = blockIdx.y * 32;
    const int tx = threadIdx.x & 31, ty8 = threadIdx.x >> 5;
    #pragma unroll
    for (int i = 0; i < 4; i++) {
        int k = ty8 + i * 8;
        t[k][tx] = rna_tf32(Wp[(size_t)(k0 + k) * EE + n0 + tx]);
    }
    __syncthreads();
    #pragma unroll
    for (int i = 0; i < 4; i++) {
        int nr = ty8 + i * 8;
        g_wpt[(size_t)(n0 + nr) * EE + k0 + tx] = t[tx][nr];
    }
}

// ============================ mma.sync GEMM core (R5, passed) =============
#define PITCH   20
#define STAGE_F (2*128*PITCH)      // 5120 floats per stage
#define GSMEM_BYTES (3*STAGE_F*4)  // 61440

__device__ __forceinline__ void gemm_load_stage(
    uint32_t smem_u32, int s, const float* __restrict__ Ag, const float* __restrict__ Bg,
    int m0, int n0, int kt, int tid)
{
    const uint32_t baseA = smem_u32 + s * (STAGE_F * 4);
    const uint32_t baseB = baseA + 128 * PITCH * 4;
    #pragma unroll
    for (int i = 0; i < 2; i++) {
        int cid = tid + i * 256;
        int r = cid >> 2, c = cid & 3;
        ldgsts16(baseA + (r * PITCH + c * 4) * 4, Ag + (size_t)(m0 + r) * EE + kt * 16 + c * 4);
        ldgsts16(baseB + (r * PITCH + c * 4) * 4, Bg + (size_t)(n0 + r) * EE + kt * 16 + c * 4);
    }
    CP_COMMIT();
}

__device__ __forceinline__ void gemm_mainloop_mma(
    const float* __restrict__ Ag, const float* __restrict__ Bg,
    int m0, int n0, float acc[2][8][4], float* __restrict__ sm)
{
    const int tid  = threadIdx.x;
    const int lane = tid & 31, wid = tid >> 5;
    const int g = lane >> 2, t4 = lane & 3;
    const int wm = wid & 3, wn = wid >> 2;
    const uint32_t smem_u32 = smem_to_u32(sm);

    gemm_load_stage(smem_u32, 0, Ag, Bg, m0, n0, 0, tid);
    gemm_load_stage(smem_u32, 1, Ag, Bg, m0, n0, 1, tid);

    const int KT = EE / 16;   // 64
    for (int t = 0; t < KT; t++) {
        const int s = t % 3;
        if (t + 2 < KT) gemm_load_stage(smem_u32, (t + 2) % 3, Ag, Bg, m0, n0, t + 2, tid);
        else            CP_COMMIT();
        CP_WAIT2();
        __syncthreads();

        const float* As = sm + s * STAGE_F;
        const float* Bs = As + 128 * PITCH;
        #pragma unroll
        for (int ks = 0; ks < 16; ks += 8) {
            uint32_t af[2][4], bf[8][2];
            #pragma unroll
            for (int mt = 0; mt < 2; mt++) {
                const int r = wm * 32 + mt * 16 + g;
                af[mt][0] = __float_as_uint(As[r * PITCH + ks + t4]);
                af[mt][1] = __float_as_uint(As[(r + 8) * PITCH + ks + t4]);
                af[mt][2] = __float_as_uint(As[r * PITCH + ks + t4 + 4]);
                af[mt][3] = __float_as_uint(As[(r + 8) * PITCH + ks + t4 + 4]);
            }
            #pragma unroll
            for (int nt = 0; nt < 8; nt++) {
                const int n = wn * 64 + nt * 8 + g;
                bf[nt][0] = __float_as_uint(Bs[n * PITCH + ks + t4]);
                bf[nt][1] = __float_as_uint(Bs[n * PITCH + ks + t4 + 4]);
            }
            #pragma unroll
            for (int mt = 0; mt < 2; mt++)
                #pragma unroll
                for (int nt = 0; nt < 8; nt++)
                    mma16n8k8(acc[mt][nt], af[mt], bf[nt]);
        }
        __syncthreads();
    }
}

// ---------------------------------------------------------------------------
// QKV projection: scatter + bias into g_q/g_k/g_v (rna-rounded for attn mma).
// ---------------------------------------------------------------------------
__global__ __launch_bounds__(256) void gemm_proj_kernel(
    const float* __restrict__ bq, const float* __restrict__ bk, const float* __restrict__ bv)
{
    extern __shared__ __align__(16) float sm[];
    const int n0 = blockIdx.x * 128;
    const int m0 = blockIdx.y * 128;

    float acc[2][8][4] = {};
    gemm_mainloop_mma(g_xr, g_wt, m0, n0, acc, sm);

    const int which = n0 >> 10;
    const int h0 = (n0 & 1023) >> 6;
    const float* bias = (which == 0) ? bq : (which == 1) ? bk : bv;
    float*       outp = (which == 0) ? g_q : (which == 1) ? g_k : g_v;

    const int lane = threadIdx.x & 31, wid = threadIdx.x >> 5;
    const int g = lane >> 2, t4 = lane & 3;
    const int wm = wid & 3, wn = wid >> 2;
    const int hh = h0 + wn;

    #pragma unroll
    for (int mt = 0; mt < 2; mt++) {
        #pragma unroll
        for (int half = 0; half < 2; half++) {
            const int row = m0 + wm * 32 + mt * 16 + g + half * 8;
            const int bi = row >> 11, sidx = row & (SS - 1);
            float* dst = &outp[(((size_t)(bi * HH + hh)) * SS + sidx) * DD];
            #pragma unroll
            for (int nt = 0; nt < 8; nt++) {
                const int d = nt * 8 + t4 * 2;
                float2 rv;
                rv.x = rna_tf32(acc[mt][nt][half * 2 + 0] + bias[hh * DD + d + 0]);
                rv.y = rna_tf32(acc[mt][nt][half * 2 + 1] + bias[hh * DD + d + 1]);
                *(float2*)&dst[d] = rv;
            }
        }
    }
}

// ---------------------------------------------------------------------------
// Output projection: out = relu(g_attn @ g_wpt^T + bp)
// ---------------------------------------------------------------------------
__global__ __launch_bounds__(256) void gemm_out_kernel(
    const float* __restrict__ bp, float* __restrict__ out)
{
    extern __shared__ __align__(16) float sm[];
    const int n0 = blockIdx.x * 128;
    const int m0 = blockIdx.y * 128;

    float acc[2][8][4] = {};
    gemm_mainloop_mma(g_attn, g_wpt, m0, n0, acc, sm);

    const int lane = threadIdx.x & 31, wid = threadIdx.x >> 5;
    const int g = lane >> 2, t4 = lane & 3;
    const int wm = wid & 3, wn = wid >> 2;

    #pragma unroll
    for (int mt = 0; mt < 2; mt++) {
        #pragma unroll
        for (int half = 0; half < 2; half++) {
            const int row = m0 + wm * 32 + mt * 16 + g + half * 8;
            float* dst = &out[(size_t)row * EE + n0 + wn * 64];
            const float* bptr = &bp[n0 + wn * 64];
            #pragma unroll
            for (int nt = 0; nt < 8; nt++) {
                const int c = nt * 8 + t4 * 2;
                float2 rv;
                rv.x = fmaxf(acc[mt][nt][half * 2 + 0] + bptr[c + 0], 0.f);
                rv.y = fmaxf(acc[mt][nt][half * 2 + 1] + bptr[c + 1], 0.f);
                *(float2*)&dst[c] = rv;
            }
        }
    }
}

// ---------------------------------------------------------------------------
// Causal flash attention, tf32 mma.sync. One block = 128 q rows of one (b,h).
// 8 warps; warp w owns m-rows w*16..+16 (m16 slab), full n.
// P never touches smem: the S-fragment -> PV-A-fragment exchange is intra-warp
// and done with shfl (producer lane (g,t4p) reg j -> consumer lane (g,t4)).
// smem (floats): Qs[128][68] | Ks[128][68] | Vs[128][72] = 26624 fl = 106496 B
// => 2 CTAs/SM (occupancy 2x vs R6).
// ---------------------------------------------------------------------------
#define ASMEM_BYTES 106496

__global__ __launch_bounds__(256, 2) void attn_mma_kernel()
{
    extern __shared__ float smf[];
    float* Qs = smf;            // [q][d]  pitch 68
    float* Ks = smf + 8704;     // [kv][d] pitch 68
    float* Vs = smf + 17408;    // [t][d]  pitch 72

    const int qt = gridDim.x - 1 - blockIdx.x;   // heavy tiles first
    const int h  = blockIdx.y;
    const int b  = blockIdx.z;
    const int q0 = qt * 128;

    const float* Q = g_q + ((size_t)(b * HH + h)) * SS * DD;
    const float* K = g_k + ((size_t)(b * HH + h)) * SS * DD;
    const float* V = g_v + ((size_t)(b * HH + h)) * SS * DD;

    const int tid = threadIdx.x;
    const int lane = tid & 31, w = tid >> 5;
    const int g = lane >> 2, t4 = lane & 3;
    const int r0l = w * 16 + g;               // local rows r0l, r0l+8
    const int src0 = (lane & ~3) | (t4 >> 1); // P-exchange source lanes
    const int src2 = src0 + 2;
    const bool odd = (t4 & 1);

    // load Q tile (coalesced, conflict-free)
    #pragma unroll
    for (int ii = 0; ii < 32; ii++) {
        int idx = tid + ii * 256;
        int r = idx >> 6, e = idx & 63;
        Qs[r * 68 + e] = Q[(size_t)(q0 + r) * DD + e];
    }

    float oacc[8][4] = {};
    float m0r = -1e30f, m1r = -1e30f, l0r = 0.f, l1r = 0.f;

    for (int kt = 0; kt <= qt; kt++) {
        __syncthreads();   // prev iter done reading Ks/Vs (and Qs stores on iter 0)
        #pragma unroll
        for (int ii = 0; ii < 32; ii++) {
            int idx = tid + ii * 256;
            int c = idx >> 6, e = idx & 63;
            Ks[c * 68 + e] = K[(size_t)(kt * 128 + c) * DD + e];
            Vs[c * 72 + e] = V[(size_t)(kt * 128 + c) * DD + e];
        }
        __syncthreads();

        // ---- S = Q K^T : 16 n-tiles x 8 k-steps of m16n8k8 ----
        float sacc[16][4];
        #pragma unroll
        for (int nt = 0; nt < 16; nt++)
            #pragma unroll
            for (int j = 0; j < 4; j++) sacc[nt][j] = 0.f;

        #pragma unroll
        for (int kd = 0; kd < 8; kd++) {
            uint32_t af[4];
            af[0] = __float_as_uint(Qs[r0l * 68 + kd * 8 + t4]);
            af[1] = __float_as_uint(Qs[(r0l + 8) * 68 + kd * 8 + t4]);
            af[2] = __float_as_uint(Qs[r0l * 68 + kd * 8 + t4 + 4]);
            af[3] = __float_as_uint(Qs[(r0l + 8) * 68 + kd * 8 + t4 + 4]);
            #pragma unroll
            for (int nt = 0; nt < 16; nt++) {
                uint32_t bf[2];
                bf[0] = __float_as_uint(Ks[(nt * 8 + g) * 68 + kd * 8 + t4]);
                bf[1] = __float_as_uint(Ks[(nt * 8 + g) * 68 + kd * 8 + t4 + 4]);
                mma16n8k8(sacc[nt], af, bf);
            }
        }

        // ---- scale + causal mask ----
        const bool diag = (kt == qt);
        #pragma unroll
        for (int nt = 0; nt < 16; nt++) {
            #pragma unroll
            for (int j = 0; j < 4; j++) {
                int c  = nt * 8 + t4 * 2 + (j & 1);
                int rl = r0l + ((j >> 1) * 8);
                float sv = sacc[nt][j] * 0.125f;
                if (diag && c > rl) sv = -1e30f;
                sacc[nt][j] = sv;
            }
        }

        // ---- online softmax (rows g and g+8 of warp slab) ----
        float mx0 = -1e30f, mx1 = -1e30f;
        #pragma unroll
        for (int nt = 0; nt < 16; nt++) {
            mx0 = fmaxf(mx0, fmaxf(sacc[nt][0], sacc[nt][1]));
            mx1 = fmaxf(mx1, fmaxf(sacc[nt][2], sacc[nt][3]));
        }
        mx0 = fmaxf(mx0, __shfl_xor_sync(0xffffffffu, mx0, 1));
        mx0 = fmaxf(mx0, __shfl_xor_sync(0xffffffffu, mx0, 2));
        mx1 = fmaxf(mx1, __shfl_xor_sync(0xffffffffu, mx1, 1));
        mx1 = fmaxf(mx1, __shfl_xor_sync(0xffffffffu, mx1, 2));

        float mn0 = fmaxf(m0r, mx0), mn1 = fmaxf(m1r, mx1);
        float f0 = __expf(m0r - mn0), f1 = __expf(m1r - mn1);
        m0r = mn0; m1r = mn1;

        float s0 = 0.f, s1 = 0.f;
        #pragma unroll
        for (int nt = 0; nt < 16; nt++) {
            float p0 = __expf(sacc[nt][0] - mn0);
            float p1 = __expf(sacc[nt][1] - mn0);
            float p2 = __expf(sacc[nt][2] - mn1);
            float p3 = __expf(sacc[nt][3] - mn1);
            s0 += p0 + p1; s1 += p2 + p3;
            // round to tf32 grid once at the producer (PV mma truncates operands)
            sacc[nt][0] = rna_tf32(p0); sacc[nt][1] = rna_tf32(p1);
            sacc[nt][2] = rna_tf32(p2); sacc[nt][3] = rna_tf32(p3);
        }
        s0 += __shfl_xor_sync(0xffffffffu, s0, 1);
        s0 += __shfl_xor_sync(0xffffffffu, s0, 2);
        s1 += __shfl_xor_sync(0xffffffffu, s1, 1);
        s1 += __shfl_xor_sync(0xffffffffu, s1, 2);
        l0r = l0r * f0 + s0;
        l1r = l1r * f1 + s1;

        #pragma unroll
        for (int nt = 0; nt < 8; nt++) {
            oacc[nt][0] *= f0; oacc[nt][1] *= f0;
            oacc[nt][2] *= f1; oacc[nt][3] *= f1;
        }

        // ---- O += P V : P delivered by intra-warp shfl, V from smem ----
        #pragma unroll
        for (int ks = 0; ks < 16; ks++) {
            // af[0] = P[r0l][ks*8+t4], af[1] = P[r0l+8][..], af[2]/[3] = +4 cols
            float a0j0 = __shfl_sync(0xffffffffu, sacc[ks][0], src0);
            float a0j1 = __shfl_sync(0xffffffffu, sacc[ks][1], src0);
            float a1j0 = __shfl_sync(0xffffffffu, sacc[ks][2], src0);
            float a1j1 = __shfl_sync(0xffffffffu, sacc[ks][3], src0);
            float a2j0 = __shfl_sync(0xffffffffu, sacc[ks][0], src2);
            float a2j1 = __shfl_sync(0xffffffffu, sacc[ks][1], src2);
            float a3j0 = __shfl_sync(0xffffffffu, sacc[ks][2], src2);
            float a3j1 = __shfl_sync(0xffffffffu, sacc[ks][3], src2);
            uint32_t af[4];
            af[0] = __float_as_uint(odd ? a0j1 : a0j0);
            af[1] = __float_as_uint(odd ? a1j1 : a1j0);
            af[2] = __float_as_uint(odd ? a2j1 : a2j0);
            af[3] = __float_as_uint(odd ? a3j1 : a3j0);
            #pragma unroll
            for (int nt = 0; nt < 8; nt++) {
                uint32_t bf[2];
                bf[0] = __float_as_uint(Vs[(ks * 8 + t4) * 72 + nt * 8 + g]);
                bf[1] = __float_as_uint(Vs[(ks * 8 + t4 + 4) * 72 + nt * 8 + g]);
                mma16n8k8(oacc[nt], af, bf);
            }
        }
    }

    // epilogue: normalize, round, store concat-ready [B,S,H*D]
    const float inv0 = 1.0f / l0r, inv1 = 1.0f / l1r;
    const int gr0 = q0 + r0l, gr1 = gr0 + 8;
    float* dst0 = &g_attn[(((size_t)(b * SS + gr0)) * HH + h) * DD];
    float* dst1 = &g_attn[(((size_t)(b * SS + gr1)) * HH + h) * DD];
    #pragma unroll
    for (int nt = 0; nt < 8; nt++) {
        const int d = nt * 8 + t4 * 2;
        float2 r0v = make_float2(rna_tf32(oacc[nt][0] * inv0), rna_tf32(oacc[nt][1] * inv0));
        float2 r1v = make_float2(rna_tf32(oacc[nt][2] * inv1), rna_tf32(oacc[nt][3] * inv1));
        *(float2*)&dst0[d] = r0v;
        *(float2*)&dst1[d] = r1v;
    }
}

// ============================ host side ============================
extern "C" void kernel_launch(void* const* d_in, const int* in_sizes, int n_in,
                              void* d_out, int out_size)
{
    const float* x  = (const float*)d_in[0];
    const float* Wq = (const float*)d_in[1];
    const float* Wk = (const float*)d_in[2];
    const float* Wv = (const float*)d_in[3];
    const float* bq = (const float*)d_in[4];
    const float* bk = (const float*)d_in[5];
    const float* bv = (const float*)d_in[6];
    const float* Wp = (const float*)d_in[7];
    const float* bp = (const float*)d_in[8];
    float* out = (float*)d_out;
    (void)in_sizes; (void)n_in; (void)out_size;

    cudaFuncSetAttribute(gemm_proj_kernel,
                         cudaFuncAttributeMaxDynamicSharedMemorySize, GSMEM_BYTES);
    cudaFuncSetAttribute(gemm_out_kernel,
                         cudaFuncAttributeMaxDynamicSharedMemorySize, GSMEM_BYTES);
    cudaFuncSetAttribute(attn_mma_kernel,
                         cudaFuncAttributeMaxDynamicSharedMemorySize, ASMEM_BYTES);

    round_x_kernel<<<1024, 256>>>(x);
    transpose_w_kernel<<<dim3(EE / 32, DD / 32, 48), 256>>>(Wq, Wk, Wv);
    transpose_wp_kernel<<<dim3(EE / 32, EE / 32), 256>>>(Wp);

    gemm_proj_kernel<<<dim3(3 * EE / 128, MTOT / 128), 256, GSMEM_BYTES>>>(bq, bk, bv);

    attn_mma_kernel<<<dim3(SS / 128, HH, BB), 256, ASMEM_BYTES>>>();

    gemm_out_kernel<<<dim3(EE / 128, MTOT / 128), 256, GSMEM_BYTES>>>(bp, out);
}

// round 10
// speedup vs baseline: 1.1170x; 1.1170x over previous
#include <cuda_runtime.h>
#include <cstdint>

// Problem shape (fixed)
#define BB 2
#define SS 2048
#define EE 1024
#define HH 16
#define DD 64
#define MTOT (BB*SS)   // 4096

// Scratch (device globals)
__device__ float g_xr[MTOT*EE];        // x rounded to tf32 grid
__device__ float g_wt[3*EE*EE];        // W{q,k,v}^T: [which][n=h*64+d][e], rna-rounded
__device__ float g_wpt[EE*EE];         // Wp^T: [n][k], rna-rounded
__device__ float g_q[BB*HH*SS*DD];     // [B,H,S,D], rna-rounded
__device__ float g_k[BB*HH*SS*DD];
__device__ float g_v[BB*HH*SS*DD];
__device__ float g_attn[BB*SS*HH*DD];  // [B,S,H*D], rna-rounded

// ============================ helpers ============================
__device__ __forceinline__ uint32_t smem_to_u32(const void* p) {
    uint32_t a;
    asm("{ .reg .u64 t; cvta.to.shared.u64 t, %1; cvt.u32.u64 %0, t; }" : "=r"(a) : "l"(p));
    return a;
}
__device__ __forceinline__ float rna_tf32(float v) {
    float r; asm("cvt.rna.tf32.f32 %0, %1;" : "=f"(r) : "f"(v)); return r;
}
__device__ __forceinline__ void ldgsts16(uint32_t s, const float* g) {
    asm volatile("cp.async.cg.shared.global [%0], [%1], 16;" :: "r"(s), "l"(g) : "memory");
}
#define CP_COMMIT() asm volatile("cp.async.commit_group;" ::: "memory")
#define CP_WAIT2()  asm volatile("cp.async.wait_group 2;" ::: "memory")

// m16n8k8 tf32 mma: D += A*B   (fragment conventions validated in R5/R6)
__device__ __forceinline__ void mma16n8k8(float* d, const uint32_t* a, const uint32_t* b) {
    asm volatile(
        "mma.sync.aligned.m16n8k8.row.col.f32.tf32.tf32.f32 "
        "{%0,%1,%2,%3}, {%4,%5,%6,%7}, {%8,%9}, {%0,%1,%2,%3};\n"
        : "+f"(d[0]), "+f"(d[1]), "+f"(d[2]), "+f"(d[3])
        : "r"(a[0]), "r"(a[1]), "r"(a[2]), "r"(a[3]), "r"(b[0]), "r"(b[1]));
}

// ============================ prep kernels ============================
__global__ __launch_bounds__(256) void round_x_kernel(const float* __restrict__ x)
{
    int i = blockIdx.x * blockDim.x + threadIdx.x;
    const int n4 = MTOT * EE / 4;
    for (; i < n4; i += gridDim.x * blockDim.x) {
        float4 v = ((const float4*)x)[i];
        v.x = rna_tf32(v.x); v.y = rna_tf32(v.y);
        v.z = rna_tf32(v.z); v.w = rna_tf32(v.w);
        ((float4*)g_xr)[i] = v;
    }
}

__global__ __launch_bounds__(256) void transpose_w_kernel(
    const float* __restrict__ Wq, const float* __restrict__ Wk, const float* __restrict__ Wv)
{
    __shared__ float t[32][33];
    const int zc = blockIdx.z;              // 0..47
    const int which = zc >> 4, h = zc & 15;
    const float* W = ((which == 0) ? Wq : (which == 1) ? Wk : Wv) + (size_t)h * EE * DD;
    const int e0 = blockIdx.x * 32, d0 = blockIdx.y * 32;
    const int tx = threadIdx.x & 31, ty8 = threadIdx.x >> 5;
    #pragma unroll
    for (int i = 0; i < 4; i++) {
        int e = ty8 + i * 8;
        t[e][tx] = rna_tf32(W[(size_t)(e0 + e) * DD + d0 + tx]);
    }
    __syncthreads();
    float* dst = g_wt + (size_t)which * EE * EE;
    #pragma unroll
    for (int i = 0; i < 4; i++) {
        int dr = ty8 + i * 8;
        dst[(size_t)(h * DD + d0 + dr) * EE + e0 + tx] = t[tx][dr];
    }
}

__global__ __launch_bounds__(256) void transpose_wp_kernel(const float* __restrict__ Wp)
{
    __shared__ float t[32][33];
    const int k0 = blockIdx.x * 32, n0 = blockIdx.y * 32;
    const int tx = threadIdx.x & 31, ty8 = threadIdx.x >> 5;
    #pragma unroll
    for (int i = 0; i < 4; i++) {
        int k = ty8 + i * 8;
        t[k][tx] = rna_tf32(Wp[(size_t)(k0 + k) * EE + n0 + tx]);
    }
    __syncthreads();
    #pragma unroll
    for (int i = 0; i < 4; i++) {
        int nr = ty8 + i * 8;
        g_wpt[(size_t)(n0 + nr) * EE + k0 + tx] = t[tx][nr];
    }
}

// ============================ mma.sync GEMM core ============================
// 4-stage cp.async pipeline, ONE __syncthreads per k-tile.
// Iter t: wait(stage t ready) -> sync -> issue loads for stage t+3 -> MMA on t.
// With 4 stages the store at iter t targets stage (t-1)&3, whose readers all
// passed the sync at top of iter t => single barrier is sufficient.
#define PITCH   20
#define STAGE_F (2*128*PITCH)      // 5120 floats per stage
#define GSMEM_BYTES (4*STAGE_F*4)  // 81920

__device__ __forceinline__ void gemm_load_stage(
    uint32_t smem_u32, int s, const float* __restrict__ Ag, const float* __restrict__ Bg,
    int m0, int n0, int kt, int tid)
{
    const uint32_t baseA = smem_u32 + s * (STAGE_F * 4);
    const uint32_t baseB = baseA + 128 * PITCH * 4;
    #pragma unroll
    for (int i = 0; i < 2; i++) {
        int cid = tid + i * 256;
        int r = cid >> 2, c = cid & 3;
        ldgsts16(baseA + (r * PITCH + c * 4) * 4, Ag + (size_t)(m0 + r) * EE + kt * 16 + c * 4);
        ldgsts16(baseB + (r * PITCH + c * 4) * 4, Bg + (size_t)(n0 + r) * EE + kt * 16 + c * 4);
    }
    CP_COMMIT();
}

__device__ __forceinline__ void gemm_mainloop_mma(
    const float* __restrict__ Ag, const float* __restrict__ Bg,
    int m0, int n0, float acc[2][8][4], float* __restrict__ sm)
{
    const int tid  = threadIdx.x;
    const int lane = tid & 31, wid = tid >> 5;
    const int g = lane >> 2, t4 = lane & 3;
    const int wm = wid & 3, wn = wid >> 2;
    const uint32_t smem_u32 = smem_to_u32(sm);

    gemm_load_stage(smem_u32, 0, Ag, Bg, m0, n0, 0, tid);
    gemm_load_stage(smem_u32, 1, Ag, Bg, m0, n0, 1, tid);
    gemm_load_stage(smem_u32, 2, Ag, Bg, m0, n0, 2, tid);

    const int KT = EE / 16;   // 64
    for (int t = 0; t < KT; t++) {
        const int s = t & 3;
        CP_WAIT2();            // stage t's group complete (<=2 groups pending)
        __syncthreads();       // stage t visible to all; readers of stage (t-1)&3 done

        if (t + 3 < KT) gemm_load_stage(smem_u32, (t + 3) & 3, Ag, Bg, m0, n0, t + 3, tid);
        else            CP_COMMIT();   // keep one-group-per-iter accounting

        const float* As = sm + s * STAGE_F;
        const float* Bs = As + 128 * PITCH;
        #pragma unroll
        for (int ks = 0; ks < 16; ks += 8) {
            uint32_t af[2][4], bf[8][2];
            #pragma unroll
            for (int mt = 0; mt < 2; mt++) {
                const int r = wm * 32 + mt * 16 + g;
                af[mt][0] = __float_as_uint(As[r * PITCH + ks + t4]);
                af[mt][1] = __float_as_uint(As[(r + 8) * PITCH + ks + t4]);
                af[mt][2] = __float_as_uint(As[r * PITCH + ks + t4 + 4]);
                af[mt][3] = __float_as_uint(As[(r + 8) * PITCH + ks + t4 + 4]);
            }
            #pragma unroll
            for (int nt = 0; nt < 8; nt++) {
                const int n = wn * 64 + nt * 8 + g;
                bf[nt][0] = __float_as_uint(Bs[n * PITCH + ks + t4]);
                bf[nt][1] = __float_as_uint(Bs[n * PITCH + ks + t4 + 4]);
            }
            #pragma unroll
            for (int mt = 0; mt < 2; mt++)
                #pragma unroll
                for (int nt = 0; nt < 8; nt++)
                    mma16n8k8(acc[mt][nt], af[mt], bf[nt]);
        }
    }
}

// ---------------------------------------------------------------------------
// QKV projection: scatter + bias into g_q/g_k/g_v (rna-rounded for attn mma).
// ---------------------------------------------------------------------------
__global__ __launch_bounds__(256) void gemm_proj_kernel(
    const float* __restrict__ bq, const float* __restrict__ bk, const float* __restrict__ bv)
{
    extern __shared__ __align__(16) float sm[];
    const int n0 = blockIdx.x * 128;
    const int m0 = blockIdx.y * 128;

    float acc[2][8][4] = {};
    gemm_mainloop_mma(g_xr, g_wt, m0, n0, acc, sm);

    const int which = n0 >> 10;
    const int h0 = (n0 & 1023) >> 6;
    const float* bias = (which == 0) ? bq : (which == 1) ? bk : bv;
    float*       outp = (which == 0) ? g_q : (which == 1) ? g_k : g_v;

    const int lane = threadIdx.x & 31, wid = threadIdx.x >> 5;
    const int g = lane >> 2, t4 = lane & 3;
    const int wm = wid & 3, wn = wid >> 2;
    const int hh = h0 + wn;

    #pragma unroll
    for (int mt = 0; mt < 2; mt++) {
        #pragma unroll
        for (int half = 0; half < 2; half++) {
            const int row = m0 + wm * 32 + mt * 16 + g + half * 8;
            const int bi = row >> 11, sidx = row & (SS - 1);
            float* dst = &outp[(((size_t)(bi * HH + hh)) * SS + sidx) * DD];
            #pragma unroll
            for (int nt = 0; nt < 8; nt++) {
                const int d = nt * 8 + t4 * 2;
                float2 rv;
                rv.x = rna_tf32(acc[mt][nt][half * 2 + 0] + bias[hh * DD + d + 0]);
                rv.y = rna_tf32(acc[mt][nt][half * 2 + 1] + bias[hh * DD + d + 1]);
                *(float2*)&dst[d] = rv;
            }
        }
    }
}

// ---------------------------------------------------------------------------
// Output projection: out = relu(g_attn @ g_wpt^T + bp)
// ---------------------------------------------------------------------------
__global__ __launch_bounds__(256) void gemm_out_kernel(
    const float* __restrict__ bp, float* __restrict__ out)
{
    extern __shared__ __align__(16) float sm[];
    const int n0 = blockIdx.x * 128;
    const int m0 = blockIdx.y * 128;

    float acc[2][8][4] = {};
    gemm_mainloop_mma(g_attn, g_wpt, m0, n0, acc, sm);

    const int lane = threadIdx.x & 31, wid = threadIdx.x >> 5;
    const int g = lane >> 2, t4 = lane & 3;
    const int wm = wid & 3, wn = wid >> 2;

    #pragma unroll
    for (int mt = 0; mt < 2; mt++) {
        #pragma unroll
        for (int half = 0; half < 2; half++) {
            const int row = m0 + wm * 32 + mt * 16 + g + half * 8;
            float* dst = &out[(size_t)row * EE + n0 + wn * 64];
            const float* bptr = &bp[n0 + wn * 64];
            #pragma unroll
            for (int nt = 0; nt < 8; nt++) {
                const int c = nt * 8 + t4 * 2;
                float2 rv;
                rv.x = fmaxf(acc[mt][nt][half * 2 + 0] + bptr[c + 0], 0.f);
                rv.y = fmaxf(acc[mt][nt][half * 2 + 1] + bptr[c + 1], 0.f);
                *(float2*)&dst[c] = rv;
            }
        }
    }
}

// ---------------------------------------------------------------------------
// Causal flash attention, tf32 mma.sync — EXACT R7 version (best: 539.3us).
// 8 warps; warp w owns m-rows w*16..+16 (m16 slab), full n. P via smem Ps.
// smem (floats): Qs[128][68] | Ks[128][68] | Vs[128][72] | Ps[128][132]
// = 43520 floats = 174080 B.
// ---------------------------------------------------------------------------
#define ASMEM_BYTES 174080

__global__ __launch_bounds__(256, 1) void attn_mma_kernel()
{
    extern __shared__ float smf[];
    float* Qs = smf;            // [q][d]  pitch 68
    float* Ks = smf + 8704;     // [kv][d] pitch 68
    float* Vs = smf + 17408;    // [t][d]  pitch 72
    float* Ps = smf + 26624;    // [q][t]  pitch 132

    const int qt = gridDim.x - 1 - blockIdx.x;   // heavy tiles first
    const int h  = blockIdx.y;
    const int b  = blockIdx.z;
    const int q0 = qt * 128;

    const float* Q = g_q + ((size_t)(b * HH + h)) * SS * DD;
    const float* K = g_k + ((size_t)(b * HH + h)) * SS * DD;
    const float* V = g_v + ((size_t)(b * HH + h)) * SS * DD;

    const int tid = threadIdx.x;
    const int lane = tid & 31, w = tid >> 5;
    const int g = lane >> 2, t4 = lane & 3;
    const int r0l = w * 16 + g;          // local row (and +8)

    // load Q tile (coalesced, conflict-free)
    #pragma unroll
    for (int ii = 0; ii < 32; ii++) {
        int idx = tid + ii * 256;
        int r = idx >> 6, e = idx & 63;
        Qs[r * 68 + e] = Q[(size_t)(q0 + r) * DD + e];
    }

    float oacc[8][4] = {};
    float m0r = -1e30f, m1r = -1e30f, l0r = 0.f, l1r = 0.f;

    for (int kt = 0; kt <= qt; kt++) {
        __syncthreads();   // prev iter done with Ks/Vs/Ps (and Qs stores on iter 0)
        #pragma unroll
        for (int ii = 0; ii < 32; ii++) {
            int idx = tid + ii * 256;
            int c = idx >> 6, e = idx & 63;
            Ks[c * 68 + e] = K[(size_t)(kt * 128 + c) * DD + e];
            Vs[c * 72 + e] = V[(size_t)(kt * 128 + c) * DD + e];
        }
        __syncthreads();

        // ---- S = Q K^T : 16 n-tiles x 8 k-steps of m16n8k8 ----
        float sacc[16][4];
        #pragma unroll
        for (int nt = 0; nt < 16; nt++)
            #pragma unroll
            for (int j = 0; j < 4; j++) sacc[nt][j] = 0.f;

        #pragma unroll
        for (int kd = 0; kd < 8; kd++) {
            uint32_t af[4];
            af[0] = __float_as_uint(Qs[r0l * 68 + kd * 8 + t4]);
            af[1] = __float_as_uint(Qs[(r0l + 8) * 68 + kd * 8 + t4]);
            af[2] = __float_as_uint(Qs[r0l * 68 + kd * 8 + t4 + 4]);
            af[3] = __float_as_uint(Qs[(r0l + 8) * 68 + kd * 8 + t4 + 4]);
            #pragma unroll
            for (int nt = 0; nt < 16; nt++) {
                uint32_t bf[2];
                bf[0] = __float_as_uint(Ks[(nt * 8 + g) * 68 + kd * 8 + t4]);
                bf[1] = __float_as_uint(Ks[(nt * 8 + g) * 68 + kd * 8 + t4 + 4]);
                mma16n8k8(sacc[nt], af, bf);
            }
        }

        // ---- scale + causal mask ----
        const bool diag = (kt == qt);
        #pragma unroll
        for (int nt = 0; nt < 16; nt++) {
            #pragma unroll
            for (int j = 0; j < 4; j++) {
                int c  = nt * 8 + t4 * 2 + (j & 1);
                int rl = r0l + ((j >> 1) * 8);
                float sv = sacc[nt][j] * 0.125f;
                if (diag && c > rl) sv = -1e30f;
                sacc[nt][j] = sv;
            }
        }

        // ---- online softmax (rows g and g+8 of warp slab) ----
        float mx0 = -1e30f, mx1 = -1e30f;
        #pragma unroll
        for (int nt = 0; nt < 16; nt++) {
            mx0 = fmaxf(mx0, fmaxf(sacc[nt][0], sacc[nt][1]));
            mx1 = fmaxf(mx1, fmaxf(sacc[nt][2], sacc[nt][3]));
        }
        mx0 = fmaxf(mx0, __shfl_xor_sync(0xffffffffu, mx0, 1));
        mx0 = fmaxf(mx0, __shfl_xor_sync(0xffffffffu, mx0, 2));
        mx1 = fmaxf(mx1, __shfl_xor_sync(0xffffffffu, mx1, 1));
        mx1 = fmaxf(mx1, __shfl_xor_sync(0xffffffffu, mx1, 2));

        float mn0 = fmaxf(m0r, mx0), mn1 = fmaxf(m1r, mx1);
        float f0 = __expf(m0r - mn0), f1 = __expf(m1r - mn1);
        m0r = mn0; m1r = mn1;

        float s0 = 0.f, s1 = 0.f;
        #pragma unroll
        for (int nt = 0; nt < 16; nt++) {
            float p0 = __expf(sacc[nt][0] - mn0);
            float p1 = __expf(sacc[nt][1] - mn0);
            float p2 = __expf(sacc[nt][2] - mn1);
            float p3 = __expf(sacc[nt][3] - mn1);
            sacc[nt][0] = p0; sacc[nt][1] = p1; sacc[nt][2] = p2; sacc[nt][3] = p3;
            s0 += p0 + p1; s1 += p2 + p3;
        }
        s0 += __shfl_xor_sync(0xffffffffu, s0, 1);
        s0 += __shfl_xor_sync(0xffffffffu, s0, 2);
        s1 += __shfl_xor_sync(0xffffffffu, s1, 1);
        s1 += __shfl_xor_sync(0xffffffffu, s1, 2);
        l0r = l0r * f0 + s0;
        l1r = l1r * f1 + s1;

        #pragma unroll
        for (int nt = 0; nt < 8; nt++) {
            oacc[nt][0] *= f0; oacc[nt][1] *= f0;
            oacc[nt][2] *= f1; oacc[nt][3] *= f1;
        }

        // ---- write P to smem (rna-rounded: mma truncates operands) ----
        #pragma unroll
        for (int nt = 0; nt < 16; nt++) {
            float2 p01 = make_float2(rna_tf32(sacc[nt][0]), rna_tf32(sacc[nt][1]));
            float2 p23 = make_float2(rna_tf32(sacc[nt][2]), rna_tf32(sacc[nt][3]));
            *(float2*)&Ps[r0l * 132 + nt * 8 + t4 * 2]       = p01;
            *(float2*)&Ps[(r0l + 8) * 132 + nt * 8 + t4 * 2] = p23;
        }
        __syncthreads();

        // ---- O += P V : 16 k-steps x 8 n-tiles ----
        #pragma unroll
        for (int ks = 0; ks < 16; ks++) {
            uint32_t af[4];
            af[0] = __float_as_uint(Ps[r0l * 132 + ks * 8 + t4]);
            af[1] = __float_as_uint(Ps[(r0l + 8) * 132 + ks * 8 + t4]);
            af[2] = __float_as_uint(Ps[r0l * 132 + ks * 8 + t4 + 4]);
            af[3] = __float_as_uint(Ps[(r0l + 8) * 132 + ks * 8 + t4 + 4]);
            #pragma unroll
            for (int nt = 0; nt < 8; nt++) {
                uint32_t bf[2];
                bf[0] = __float_as_uint(Vs[(ks * 8 + t4) * 72 + nt * 8 + g]);
                bf[1] = __float_as_uint(Vs[(ks * 8 + t4 + 4) * 72 + nt * 8 + g]);
                mma16n8k8(oacc[nt], af, bf);
            }
        }
    }

    // epilogue: normalize, round, store concat-ready [B,S,H*D]
    const float inv0 = 1.0f / l0r, inv1 = 1.0f / l1r;
    const int gr0 = q0 + r0l, gr1 = gr0 + 8;
    float* dst0 = &g_attn[(((size_t)(b * SS + gr0)) * HH + h) * DD];
    float* dst1 = &g_attn[(((size_t)(b * SS + gr1)) * HH + h) * DD];
    #pragma unroll
    for (int nt = 0; nt < 8; nt++) {
        const int d = nt * 8 + t4 * 2;
        float2 r0v = make_float2(rna_tf32(oacc[nt][0] * inv0), rna_tf32(oacc[nt][1] * inv0));
        float2 r1v = make_float2(rna_tf32(oacc[nt][2] * inv1), rna_tf32(oacc[nt][3] * inv1));
        *(float2*)&dst0[d] = r0v;
        *(float2*)&dst1[d] = r1v;
    }
}

// ============================ host side ============================
extern "C" void kernel_launch(void* const* d_in, const int* in_sizes, int n_in,
                              void* d_out, int out_size)
{
    const float* x  = (const float*)d_in[0];
    const float* Wq = (const float*)d_in[1];
    const float* Wk = (const float*)d_in[2];
    const float* Wv = (const float*)d_in[3];
    const float* bq = (const float*)d_in[4];
    const float* bk = (const float*)d_in[5];
    const float* bv = (const float*)d_in[6];
    const float* Wp = (const float*)d_in[7];
    const float* bp = (const float*)d_in[8];
    float* out = (float*)d_out;
    (void)in_sizes; (void)n_in; (void)out_size;

    cudaFuncSetAttribute(gemm_proj_kernel,
                         cudaFuncAttributeMaxDynamicSharedMemorySize, GSMEM_BYTES);
    cudaFuncSetAttribute(gemm_out_kernel,
                         cudaFuncAttributeMaxDynamicSharedMemorySize, GSMEM_BYTES);
    cudaFuncSetAttribute(attn_mma_kernel,
                         cudaFuncAttributeMaxDynamicSharedMemorySize, ASMEM_BYTES);

    round_x_kernel<<<1024, 256>>>(x);
    transpose_w_kernel<<<dim3(EE / 32, DD / 32, 48), 256>>>(Wq, Wk, Wv);
    transpose_wp_kernel<<<dim3(EE / 32, EE / 32), 256>>>(Wp);

    gemm_proj_kernel<<<dim3(3 * EE / 128, MTOT / 128), 256, GSMEM_BYTES>>>(bq, bk, bv);

    attn_mma_kernel<<<dim3(SS / 128, HH, BB), 256, ASMEM_BYTES>>>();

    gemm_out_kernel<<<dim3(EE / 128, MTOT / 128), 256, GSMEM_BYTES>>>(bp, out);
}

// round 11
// speedup vs baseline: 1.1694x; 1.0469x over previous
#include <cuda_runtime.h>
#include <cstdint>

// Problem shape (fixed)
#define BB 2
#define SS 2048
#define EE 1024
#define HH 16
#define DD 64
#define MTOT (BB*SS)   // 4096

// Scratch (device globals)
__device__ float g_xr[MTOT*EE];        // x rounded to tf32 grid
__device__ float g_wt[3*EE*EE];        // W{q,k,v}^T: [which][n=h*64+d][e], rna-rounded
__device__ float g_wpt[EE*EE];         // Wp^T: [n][k], rna-rounded
__device__ float g_q[BB*HH*SS*DD];     // [B,H,S,D], rna-rounded
__device__ float g_k[BB*HH*SS*DD];
__device__ float g_v[BB*HH*SS*DD];
__device__ float g_attn[BB*SS*HH*DD];  // [B,S,H*D], rna-rounded

// ============================ helpers ============================
__device__ __forceinline__ uint32_t smem_to_u32(const void* p) {
    uint32_t a;
    asm("{ .reg .u64 t; cvta.to.shared.u64 t, %1; cvt.u32.u64 %0, t; }" : "=r"(a) : "l"(p));
    return a;
}
__device__ __forceinline__ float rna_tf32(float v) {
    float r; asm("cvt.rna.tf32.f32 %0, %1;" : "=f"(r) : "f"(v)); return r;
}
__device__ __forceinline__ void ldgsts16(uint32_t s, const float* g) {
    asm volatile("cp.async.cg.shared.global [%0], [%1], 16;" :: "r"(s), "l"(g) : "memory");
}
#define CP_COMMIT() asm volatile("cp.async.commit_group;" ::: "memory")
#define CP_WAIT2()  asm volatile("cp.async.wait_group 2;" ::: "memory")

// m16n8k8 tf32 mma: D += A*B   (fragment conventions validated in R5/R6)
__device__ __forceinline__ void mma16n8k8(float* d, const uint32_t* a, const uint32_t* b) {
    asm volatile(
        "mma.sync.aligned.m16n8k8.row.col.f32.tf32.tf32.f32 "
        "{%0,%1,%2,%3}, {%4,%5,%6,%7}, {%8,%9}, {%0,%1,%2,%3};\n"
        : "+f"(d[0]), "+f"(d[1]), "+f"(d[2]), "+f"(d[3])
        : "r"(a[0]), "r"(a[1]), "r"(a[2]), "r"(a[3]), "r"(b[0]), "r"(b[1]));
}

// ldmatrix x4: four 8-row x 16B matrices; lane groups 0-7/8-15/16-23/24-31
// supply row addresses for matrices 0..3 -> dest regs r[0..3].
__device__ __forceinline__ void ldm_x4(uint32_t* r, uint32_t addr) {
    asm volatile("ldmatrix.sync.aligned.m8n8.x4.shared.b16 {%0,%1,%2,%3}, [%4];"
        : "=r"(r[0]), "=r"(r[1]), "=r"(r[2]), "=r"(r[3]) : "r"(addr));
}

// ============================ prep kernels ============================
__global__ __launch_bounds__(256) void round_x_kernel(const float* __restrict__ x)
{
    int i = blockIdx.x * blockDim.x + threadIdx.x;
    const int n4 = MTOT * EE / 4;
    for (; i < n4; i += gridDim.x * blockDim.x) {
        float4 v = ((const float4*)x)[i];
        v.x = rna_tf32(v.x); v.y = rna_tf32(v.y);
        v.z = rna_tf32(v.z); v.w = rna_tf32(v.w);
        ((float4*)g_xr)[i] = v;
    }
}

__global__ __launch_bounds__(256) void transpose_w_kernel(
    const float* __restrict__ Wq, const float* __restrict__ Wk, const float* __restrict__ Wv)
{
    __shared__ float t[32][33];
    const int zc = blockIdx.z;              // 0..47
    const int which = zc >> 4, h = zc & 15;
    const float* W = ((which == 0) ? Wq : (which == 1) ? Wk : Wv) + (size_t)h * EE * DD;
    const int e0 = blockIdx.x * 32, d0 = blockIdx.y * 32;
    const int tx = threadIdx.x & 31, ty8 = threadIdx.x >> 5;
    #pragma unroll
    for (int i = 0; i < 4; i++) {
        int e = ty8 + i * 8;
        t[e][tx] = rna_tf32(W[(size_t)(e0 + e) * DD + d0 + tx]);
    }
    __syncthreads();
    float* dst = g_wt + (size_t)which * EE * EE;
    #pragma unroll
    for (int i = 0; i < 4; i++) {
        int dr = ty8 + i * 8;
        dst[(size_t)(h * DD + d0 + dr) * EE + e0 + tx] = t[tx][dr];
    }
}

__global__ __launch_bounds__(256) void transpose_wp_kernel(const float* __restrict__ Wp)
{
    __shared__ float t[32][33];
    const int k0 = blockIdx.x * 32, n0 = blockIdx.y * 32;
    const int tx = threadIdx.x & 31, ty8 = threadIdx.x >> 5;
    #pragma unroll
    for (int i = 0; i < 4; i++) {
        int k = ty8 + i * 8;
        t[k][tx] = rna_tf32(Wp[(size_t)(k0 + k) * EE + n0 + tx]);
    }
    __syncthreads();
    #pragma unroll
    for (int i = 0; i < 4; i++) {
        int nr = ty8 + i * 8;
        g_wpt[(size_t)(n0 + nr) * EE + k0 + tx] = t[tx][nr];
    }
}

// ============================ mma.sync GEMM core ============================
// 4-stage cp.async pipeline, one __syncthreads per k-tile (R9, passed).
// Fragments via ldmatrix.x4 (12 per k-tile vs 48 scalar LDS).
#define PITCH   20
#define STAGE_F (2*128*PITCH)      // 5120 floats per stage
#define GSMEM_BYTES (4*STAGE_F*4)  // 81920

__device__ __forceinline__ void gemm_load_stage(
    uint32_t smem_u32, int s, const float* __restrict__ Ag, const float* __restrict__ Bg,
    int m0, int n0, int kt, int tid)
{
    const uint32_t baseA = smem_u32 + s * (STAGE_F * 4);
    const uint32_t baseB = baseA + 128 * PITCH * 4;
    #pragma unroll
    for (int i = 0; i < 2; i++) {
        int cid = tid + i * 256;
        int r = cid >> 2, c = cid & 3;
        ldgsts16(baseA + (r * PITCH + c * 4) * 4, Ag + (size_t)(m0 + r) * EE + kt * 16 + c * 4);
        ldgsts16(baseB + (r * PITCH + c * 4) * 4, Bg + (size_t)(n0 + r) * EE + kt * 16 + c * 4);
    }
    CP_COMMIT();
}

__device__ __forceinline__ void gemm_mainloop_mma(
    const float* __restrict__ Ag, const float* __restrict__ Bg,
    int m0, int n0, float acc[2][8][4], float* __restrict__ sm)
{
    const int tid  = threadIdx.x;
    const int lane = tid & 31, wid = tid >> 5;
    const int wm = wid & 3, wn = wid >> 2;
    const uint32_t smem_u32 = smem_to_u32(sm);

    // ldmatrix per-lane row addressing
    const int Lq = lane & 7, grp = lane >> 3;
    // A x4: m0 rows +{0,8} x cols +{0,4}: grp0=(r,c0) grp1=(r+8,c0) grp2=(r,c4) grp3=(r+8,c4)
    const int offA = (wm * 32 + (grp & 1) * 8 + Lq) * PITCH + (grp >> 1) * 4;
    // B x4: grp0=(n,c0) grp1=(n,c4) grp2=(n+8,c0) grp3=(n+8,c4)
    const int offB = (wn * 64 + (grp >> 1) * 8 + Lq) * PITCH + (grp & 1) * 4;

    gemm_load_stage(smem_u32, 0, Ag, Bg, m0, n0, 0, tid);
    gemm_load_stage(smem_u32, 1, Ag, Bg, m0, n0, 1, tid);
    gemm_load_stage(smem_u32, 2, Ag, Bg, m0, n0, 2, tid);

    const int KT = EE / 16;   // 64
    for (int t = 0; t < KT; t++) {
        const int s = t & 3;
        CP_WAIT2();
        __syncthreads();

        if (t + 3 < KT) gemm_load_stage(smem_u32, (t + 3) & 3, Ag, Bg, m0, n0, t + 3, tid);
        else            CP_COMMIT();

        const uint32_t aBase = smem_u32 + s * (STAGE_F * 4);
        const uint32_t bBase = aBase + 128 * PITCH * 4;
        #pragma unroll
        for (int ks = 0; ks < 16; ks += 8) {
            uint32_t af[2][4], bf[8][2];
            ldm_x4(af[0], aBase + (offA + ks) * 4);
            ldm_x4(af[1], aBase + (offA + 16 * PITCH + ks) * 4);
            #pragma unroll
            for (int ntp = 0; ntp < 4; ntp++) {
                uint32_t tb[4];
                ldm_x4(tb, bBase + (offB + ntp * 16 * PITCH + ks) * 4);
                bf[2 * ntp][0] = tb[0]; bf[2 * ntp][1] = tb[1];
                bf[2 * ntp + 1][0] = tb[2]; bf[2 * ntp + 1][1] = tb[3];
            }
            #pragma unroll
            for (int mt = 0; mt < 2; mt++)
                #pragma unroll
                for (int nt = 0; nt < 8; nt++)
                    mma16n8k8(acc[mt][nt], af[mt], bf[nt]);
        }
    }
}

// ---------------------------------------------------------------------------
// QKV projection: scatter + bias into g_q/g_k/g_v (rna-rounded for attn mma).
// ---------------------------------------------------------------------------
__global__ __launch_bounds__(256) void gemm_proj_kernel(
    const float* __restrict__ bq, const float* __restrict__ bk, const float* __restrict__ bv)
{
    extern __shared__ __align__(16) float sm[];
    const int n0 = blockIdx.x * 128;
    const int m0 = blockIdx.y * 128;

    float acc[2][8][4] = {};
    gemm_mainloop_mma(g_xr, g_wt, m0, n0, acc, sm);

    const int which = n0 >> 10;
    const int h0 = (n0 & 1023) >> 6;
    const float* bias = (which == 0) ? bq : (which == 1) ? bk : bv;
    float*       outp = (which == 0) ? g_q : (which == 1) ? g_k : g_v;

    const int lane = threadIdx.x & 31, wid = threadIdx.x >> 5;
    const int g = lane >> 2, t4 = lane & 3;
    const int wm = wid & 3, wn = wid >> 2;
    const int hh = h0 + wn;

    #pragma unroll
    for (int mt = 0; mt < 2; mt++) {
        #pragma unroll
        for (int half = 0; half < 2; half++) {
            const int row = m0 + wm * 32 + mt * 16 + g + half * 8;
            const int bi = row >> 11, sidx = row & (SS - 1);
            float* dst = &outp[(((size_t)(bi * HH + hh)) * SS + sidx) * DD];
            #pragma unroll
            for (int nt = 0; nt < 8; nt++) {
                const int d = nt * 8 + t4 * 2;
                float2 rv;
                rv.x = rna_tf32(acc[mt][nt][half * 2 + 0] + bias[hh * DD + d + 0]);
                rv.y = rna_tf32(acc[mt][nt][half * 2 + 1] + bias[hh * DD + d + 1]);
                *(float2*)&dst[d] = rv;
            }
        }
    }
}

// ---------------------------------------------------------------------------
// Output projection: out = relu(g_attn @ g_wpt^T + bp)
// ---------------------------------------------------------------------------
__global__ __launch_bounds__(256) void gemm_out_kernel(
    const float* __restrict__ bp, float* __restrict__ out)
{
    extern __shared__ __align__(16) float sm[];
    const int n0 = blockIdx.x * 128;
    const int m0 = blockIdx.y * 128;

    float acc[2][8][4] = {};
    gemm_mainloop_mma(g_attn, g_wpt, m0, n0, acc, sm);

    const int lane = threadIdx.x & 31, wid = threadIdx.x >> 5;
    const int g = lane >> 2, t4 = lane & 3;
    const int wm = wid & 3, wn = wid >> 2;

    #pragma unroll
    for (int mt = 0; mt < 2; mt++) {
        #pragma unroll
        for (int half = 0; half < 2; half++) {
            const int row = m0 + wm * 32 + mt * 16 + g + half * 8;
            float* dst = &out[(size_t)row * EE + n0 + wn * 64];
            const float* bptr = &bp[n0 + wn * 64];
            #pragma unroll
            for (int nt = 0; nt < 8; nt++) {
                const int c = nt * 8 + t4 * 2;
                float2 rv;
                rv.x = fmaxf(acc[mt][nt][half * 2 + 0] + bptr[c + 0], 0.f);
                rv.y = fmaxf(acc[mt][nt][half * 2 + 1] + bptr[c + 1], 0.f);
                *(float2*)&dst[c] = rv;
            }
        }
    }
}

// ---------------------------------------------------------------------------
// Causal flash attention, tf32 mma.sync (R7 structure) with ldmatrix fragments.
// 8 warps; warp w owns m-rows w*16..+16 (m16 slab), full n.
// smem (floats): Qs[128][68] @0 | Ks[128][68] @8704 | Vst[64][132] @17408 |
//                Ps[128][132] @25856 ; total 42752 floats = 171008 B.
// Vst is V transposed ([d][t]) so PV's B fragment rows are 16B-contiguous.
// ---------------------------------------------------------------------------
#define ASMEM_BYTES 171008

__global__ __launch_bounds__(256, 1) void attn_mma_kernel()
{
    extern __shared__ float smf[];
    float* Qs  = smf;            // [q][d]  pitch 68
    float* Ks  = smf + 8704;     // [kv][d] pitch 68
    float* Vst = smf + 17408;    // [d][t]  pitch 132 (transposed V)
    float* Ps  = smf + 25856;    // [q][t]  pitch 132

    const int qt = gridDim.x - 1 - blockIdx.x;   // heavy tiles first
    const int h  = blockIdx.y;
    const int b  = blockIdx.z;
    const int q0 = qt * 128;

    const float* Q = g_q + ((size_t)(b * HH + h)) * SS * DD;
    const float* K = g_k + ((size_t)(b * HH + h)) * SS * DD;
    const float* V = g_v + ((size_t)(b * HH + h)) * SS * DD;

    const int tid = threadIdx.x;
    const int lane = tid & 31, w = tid >> 5;
    const int g = lane >> 2, t4 = lane & 3;
    const int r0l = w * 16 + g;          // local row (and +8)

    const uint32_t Qs_u32  = smem_to_u32(Qs);
    const uint32_t Ks_u32  = smem_to_u32(Ks);
    const uint32_t Vst_u32 = smem_to_u32(Vst);
    const uint32_t Ps_u32  = smem_to_u32(Ps);

    // ldmatrix per-lane addressing
    const int Lq = lane & 7, grp = lane >> 3;
    const int offQ = (w * 16 + (grp & 1) * 8 + Lq) * 68  + (grp >> 1) * 4;  // A frag
    const int offK = ((grp >> 1) * 8 + Lq) * 68          + (grp & 1) * 4;   // B frag
    const int offP = (w * 16 + (grp & 1) * 8 + Lq) * 132 + (grp >> 1) * 4;  // A frag
    const int offV = ((grp >> 1) * 8 + Lq) * 132         + (grp & 1) * 4;   // B frag

    // load Q tile (coalesced, conflict-free)
    #pragma unroll
    for (int ii = 0; ii < 32; ii++) {
        int idx = tid + ii * 256;
        int r = idx >> 6, e = idx & 63;
        Qs[r * 68 + e] = Q[(size_t)(q0 + r) * DD + e];
    }

    float oacc[8][4] = {};
    float m0r = -1e30f, m1r = -1e30f, l0r = 0.f, l1r = 0.f;

    for (int kt = 0; kt <= qt; kt++) {
        __syncthreads();   // prev iter done with Ks/Vst/Ps (and Qs stores on iter 0)
        #pragma unroll
        for (int ii = 0; ii < 32; ii++) {
            int idx = tid + ii * 256;
            int c = idx >> 6, e = idx & 63;
            Ks[c * 68 + e]   = K[(size_t)(kt * 128 + c) * DD + e];
            Vst[e * 132 + c] = V[(size_t)(kt * 128 + c) * DD + e];   // transpose
        }
        __syncthreads();

        // ---- S = Q K^T : 16 n-tiles x 8 k-steps of m16n8k8 ----
        float sacc[16][4];
        #pragma unroll
        for (int nt = 0; nt < 16; nt++)
            #pragma unroll
            for (int j = 0; j < 4; j++) sacc[nt][j] = 0.f;

        #pragma unroll
        for (int kd = 0; kd < 8; kd++) {
            uint32_t af[4];
            ldm_x4(af, Qs_u32 + (offQ + kd * 8) * 4);
            #pragma unroll
            for (int ntp = 0; ntp < 8; ntp++) {
                uint32_t tb[4];
                ldm_x4(tb, Ks_u32 + (offK + ntp * 16 * 68 + kd * 8) * 4);
                mma16n8k8(sacc[2 * ntp],     af, &tb[0]);
                mma16n8k8(sacc[2 * ntp + 1], af, &tb[2]);
            }
        }

        // ---- scale + causal mask ----
        const bool diag = (kt == qt);
        #pragma unroll
        for (int nt = 0; nt < 16; nt++) {
            #pragma unroll
            for (int j = 0; j < 4; j++) {
                int c  = nt * 8 + t4 * 2 + (j & 1);
                int rl = r0l + ((j >> 1) * 8);
                float sv = sacc[nt][j] * 0.125f;
                if (diag && c > rl) sv = -1e30f;
                sacc[nt][j] = sv;
            }
        }

        // ---- online softmax (rows g and g+8 of warp slab) ----
        float mx0 = -1e30f, mx1 = -1e30f;
        #pragma unroll
        for (int nt = 0; nt < 16; nt++) {
            mx0 = fmaxf(mx0, fmaxf(sacc[nt][0], sacc[nt][1]));
            mx1 = fmaxf(mx1, fmaxf(sacc[nt][2], sacc[nt][3]));
        }
        mx0 = fmaxf(mx0, __shfl_xor_sync(0xffffffffu, mx0, 1));
        mx0 = fmaxf(mx0, __shfl_xor_sync(0xffffffffu, mx0, 2));
        mx1 = fmaxf(mx1, __shfl_xor_sync(0xffffffffu, mx1, 1));
        mx1 = fmaxf(mx1, __shfl_xor_sync(0xffffffffu, mx1, 2));

        float mn0 = fmaxf(m0r, mx0), mn1 = fmaxf(m1r, mx1);
        float f0 = __expf(m0r - mn0), f1 = __expf(m1r - mn1);
        m0r = mn0; m1r = mn1;

        float s0 = 0.f, s1 = 0.f;
        #pragma unroll
        for (int nt = 0; nt < 16; nt++) {
            float p0 = __expf(sacc[nt][0] - mn0);
            float p1 = __expf(sacc[nt][1] - mn0);
            float p2 = __expf(sacc[nt][2] - mn1);
            float p3 = __expf(sacc[nt][3] - mn1);
            sacc[nt][0] = p0; sacc[nt][1] = p1; sacc[nt][2] = p2; sacc[nt][3] = p3;
            s0 += p0 + p1; s1 += p2 + p3;
        }
        s0 += __shfl_xor_sync(0xffffffffu, s0, 1);
        s0 += __shfl_xor_sync(0xffffffffu, s0, 2);
        s1 += __shfl_xor_sync(0xffffffffu, s1, 1);
        s1 += __shfl_xor_sync(0xffffffffu, s1, 2);
        l0r = l0r * f0 + s0;
        l1r = l1r * f1 + s1;

        #pragma unroll
        for (int nt = 0; nt < 8; nt++) {
            oacc[nt][0] *= f0; oacc[nt][1] *= f0;
            oacc[nt][2] *= f1; oacc[nt][3] *= f1;
        }

        // ---- write P to smem (rna-rounded: mma truncates operands) ----
        #pragma unroll
        for (int nt = 0; nt < 16; nt++) {
            float2 p01 = make_float2(rna_tf32(sacc[nt][0]), rna_tf32(sacc[nt][1]));
            float2 p23 = make_float2(rna_tf32(sacc[nt][2]), rna_tf32(sacc[nt][3]));
            *(float2*)&Ps[r0l * 132 + nt * 8 + t4 * 2]       = p01;
            *(float2*)&Ps[(r0l + 8) * 132 + nt * 8 + t4 * 2] = p23;
        }
        __syncthreads();

        // ---- O += P V : 16 k-steps x 8 n-tiles (ldmatrix fragments) ----
        #pragma unroll
        for (int ks = 0; ks < 16; ks++) {
            uint32_t af[4];
            ldm_x4(af, Ps_u32 + (offP + ks * 8) * 4);
            #pragma unroll
            for (int ntp = 0; ntp < 4; ntp++) {
                uint32_t tb[4];
                ldm_x4(tb, Vst_u32 + (offV + ntp * 16 * 132 + ks * 8) * 4);
                mma16n8k8(oacc[2 * ntp],     af, &tb[0]);
                mma16n8k8(oacc[2 * ntp + 1], af, &tb[2]);
            }
        }
    }

    // epilogue: normalize, round, store concat-ready [B,S,H*D]
    const float inv0 = 1.0f / l0r, inv1 = 1.0f / l1r;
    const int gr0 = q0 + r0l, gr1 = gr0 + 8;
    float* dst0 = &g_attn[(((size_t)(b * SS + gr0)) * HH + h) * DD];
    float* dst1 = &g_attn[(((size_t)(b * SS + gr1)) * HH + h) * DD];
    #pragma unroll
    for (int nt = 0; nt < 8; nt++) {
        const int d = nt * 8 + t4 * 2;
        float2 r0v = make_float2(rna_tf32(oacc[nt][0] * inv0), rna_tf32(oacc[nt][1] * inv0));
        float2 r1v = make_float2(rna_tf32(oacc[nt][2] * inv1), rna_tf32(oacc[nt][3] * inv1));
        *(float2*)&dst0[d] = r0v;
        *(float2*)&dst1[d] = r1v;
    }
}

// ============================ host side ============================
extern "C" void kernel_launch(void* const* d_in, const int* in_sizes, int n_in,
                              void* d_out, int out_size)
{
    const float* x  = (const float*)d_in[0];
    const float* Wq = (const float*)d_in[1];
    const float* Wk = (const float*)d_in[2];
    const float* Wv = (const float*)d_in[3];
    const float* bq = (const float*)d_in[4];
    const float* bk = (const float*)d_in[5];
    const float* bv = (const float*)d_in[6];
    const float* Wp = (const float*)d_in[7];
    const float* bp = (const float*)d_in[8];
    float* out = (float*)d_out;
    (void)in_sizes; (void)n_in; (void)out_size;

    cudaFuncSetAttribute(gemm_proj_kernel,
                         cudaFuncAttributeMaxDynamicSharedMemorySize, GSMEM_BYTES);
    cudaFuncSetAttribute(gemm_out_kernel,
                         cudaFuncAttributeMaxDynamicSharedMemorySize, GSMEM_BYTES);
    cudaFuncSetAttribute(attn_mma_kernel,
                         cudaFuncAttributeMaxDynamicSharedMemorySize, ASMEM_BYTES);

    round_x_kernel<<<1024, 256>>>(x);
    transpose_w_kernel<<<dim3(EE / 32, DD / 32, 48), 256>>>(Wq, Wk, Wv);
    transpose_wp_kernel<<<dim3(EE / 32, EE / 32), 256>>>(Wp);

    gemm_proj_kernel<<<dim3(3 * EE / 128, MTOT / 128), 256, GSMEM_BYTES>>>(bq, bk, bv);

    attn_mma_kernel<<<dim3(SS / 128, HH, BB), 256, ASMEM_BYTES>>>();

    gemm_out_kernel<<<dim3(EE / 128, MTOT / 128), 256, GSMEM_BYTES>>>(bp, out);
}